// round 7
// baseline (speedup 1.0000x reference)
#include <cuda_runtime.h>
#include <cuda_bf16.h>
#include <cstdint>

#define N_USER 50000
#define N_ITEM 100000
#define N_TOT  150000
#define D      64
#define NNZ    2400000
#define B_SZ   4096
#define N_LAYERS 3

#define SCAN_B 1024
#define SCAN_NBLK ((N_TOT + SCAN_B - 1) / SCAN_B)   // 147

#define ROWS_PER_BLK 16
#define LBLK (N_TOT / ROWS_PER_BLK)                 // 9375 exact

#define SAP  136   // A-plane k-stride (bf16): bank-free frag loads
#define SWP  130   // W-plane k-stride (bf16): <=2-way conflicts

// ---------------- device scratch (allocation-free rule) ----------------
__device__ float g_E0[N_TOT * D];
__device__ float g_E1[N_TOT * D];
__device__ float g_all[N_TOT * 4 * D];
__device__ int   g_cnt[N_TOT];
__device__ int   g_rowptr[N_TOT + 1];
__device__ int   g_cur[N_TOT];
__device__ int   g_bsum[SCAN_NBLK + 1];
__device__ int2  g_csr[NNZ];
__device__ __nv_bfloat16 g_Whi[N_LAYERS][64 * 128];  // [n][k], W'=[Wgc;Wbi]
__device__ __nv_bfloat16 g_Wlo[N_LAYERS][64 * 128];

// ---------------------------------------------------------------------------
__global__ void init_kernel(const float* __restrict__ user_emb,
                            const float* __restrict__ item_emb) {
    int i = blockIdx.x * blockDim.x + threadIdx.x;
    if (i >= N_TOT * D) return;
    float v = (i < N_USER * D) ? user_emb[i] : item_emb[i - N_USER * D];
    g_E0[i] = v;
    int row = i >> 6, col = i & 63;
    g_all[row * (4 * D) + col] = v;
    if (col == 0) g_cnt[row] = 0;
}

// W' -> bf16 hi/lo planes, [n][k] layout. One block per layer.
__global__ void wconv_kernel(const float* __restrict__ Wgc,
                             const float* __restrict__ Wbi) {
    int layer = blockIdx.x;
    const float* wg = Wgc + layer * 4096;
    const float* wb = Wbi + layer * 4096;
    for (int idx = threadIdx.x; idx < 64 * 128; idx += blockDim.x) {
        int n = idx >> 7, k = idx & 127;
        float w = (k < 64) ? wg[k * 64 + n] : wb[(k - 64) * 64 + n];
        __nv_bfloat16 h = __float2bfloat16(w);
        g_Whi[layer][idx] = h;
        g_Wlo[layer][idx] = __float2bfloat16(w - __bfloat162float(h));
    }
}

// ---------------------------------------------------------------------------
// CSR build
// ---------------------------------------------------------------------------
__global__ void hist_kernel(const int* __restrict__ rows) {
    int i = blockIdx.x * blockDim.x + threadIdx.x;
    if (i < NNZ) atomicAdd(&g_cnt[rows[i]], 1);
}

__global__ void scan1_kernel() {
    __shared__ int s[SCAN_B];
    int tid = threadIdx.x;
    int gid = blockIdx.x * SCAN_B + tid;
    int v = (gid < N_TOT) ? g_cnt[gid] : 0;
    s[tid] = v;
    __syncthreads();
    #pragma unroll
    for (int off = 1; off < SCAN_B; off <<= 1) {
        int t = (tid >= off) ? s[tid - off] : 0;
        __syncthreads();
        s[tid] += t;
        __syncthreads();
    }
    if (gid < N_TOT) g_rowptr[gid] = s[tid] - v;
    if (tid == SCAN_B - 1) g_bsum[blockIdx.x] = s[tid];
}

__global__ void scan2_kernel() {
    __shared__ int s[256];
    int tid = threadIdx.x;
    int v = (tid < SCAN_NBLK) ? g_bsum[tid] : 0;
    s[tid] = v;
    __syncthreads();
    #pragma unroll
    for (int off = 1; off < 256; off <<= 1) {
        int t = (tid >= off) ? s[tid - off] : 0;
        __syncthreads();
        s[tid] += t;
        __syncthreads();
    }
    if (tid < SCAN_NBLK) g_bsum[tid] = s[tid] - v;
}

__global__ void scan3_kernel() {
    int gid = blockIdx.x * SCAN_B + threadIdx.x;
    if (gid < N_TOT) {
        g_rowptr[gid] += g_bsum[blockIdx.x];
        g_cur[gid] = 0;
    }
    if (gid == 0) g_rowptr[N_TOT] = NNZ;
}

__global__ void scatter_kernel(const float* __restrict__ vals,
                               const int*   __restrict__ rows,
                               const int*   __restrict__ cols) {
    int i = blockIdx.x * blockDim.x + threadIdx.x;
    if (i >= NNZ) return;
    int r = rows[i];
    int pos = g_rowptr[r] + atomicAdd(&g_cur[r], 1);
    g_csr[pos] = make_int2(cols[i], __float_as_int(vals[i]));
}

// ---------------------------------------------------------------------------
#define MMA_BF16(C, A0, A1, A2, A3, B0, B1)                                   \
    asm volatile(                                                             \
        "mma.sync.aligned.m16n8k16.row.col.f32.bf16.bf16.f32 "                \
        "{%0,%1,%2,%3}, {%4,%5,%6,%7}, {%8,%9}, {%0,%1,%2,%3};"               \
        : "+f"(C[0]), "+f"(C[1]), "+f"(C[2]), "+f"(C[3])                      \
        : "r"(A0), "r"(A1), "r"(A2), "r"(A3), "r"(B0), "r"(B1))

__device__ __forceinline__ uint32_t pack_hi(float a, float b) {
    __nv_bfloat162 h = __floats2bfloat162_rn(a, b);
    return *reinterpret_cast<uint32_t*>(&h);
}

// ---------------------------------------------------------------------------
// FUSED layer kernel (16 rows/block):
//   Phase 0: copy W hi/lo planes to smem (padded stride SWP)
//   Phase 1: CSR SPMM (16 thr/row) -> sA = [L+E | L*E] bf16 hi/lo (stride SAP)
//   Phase 2: mma.sync GEMM (hi*hi + hi*lo + lo*hi), all operands in smem
//   Phase 3: epilogue (+2b, leaky-relu, row-norm, stores)
// ---------------------------------------------------------------------------
__global__ void __launch_bounds__(256)
fused_layer_kernel(const float* __restrict__ ego_in,
                   float*       __restrict__ ego_out,
                   const __nv_bfloat16* __restrict__ Whi,
                   const __nv_bfloat16* __restrict__ Wlo,
                   const float* __restrict__ bb,
                   int layer) {
    __shared__ __nv_bfloat16 sAhi[16 * SAP];
    __shared__ __nv_bfloat16 sAlo[16 * SAP];
    __shared__ __nv_bfloat16 sWhi[64 * SWP];
    __shared__ __nv_bfloat16 sWlo[64 * SWP];
    __shared__ float sC[16 * 64];

    int tid = threadIdx.x;
    int rowBase = blockIdx.x * ROWS_PER_BLK;

    // ---- Phase 0: stage W planes into smem (issue loads early) ----
    {
        const uint32_t* srcH = (const uint32_t*)Whi;   // 64 words/row
        const uint32_t* srcL = (const uint32_t*)Wlo;
        uint32_t* dH = (uint32_t*)sWhi;                // 65 words/row
        uint32_t* dL = (uint32_t*)sWlo;
        #pragma unroll
        for (int p = 0; p < 16; p++) {
            int i = p * 256 + tid;          // 4096 words per plane
            int n = i >> 6, kw = i & 63;
            dH[n * 65 + kw] = __ldg(&srcH[i]);
            dL[n * 65 + kw] = __ldg(&srcL[i]);
        }
    }

    // ---- Phase 1: CSR SPMM, 16 threads/row, single pass ----
    {
        int rl = tid >> 4;              // 0..15 local row
        int c  = (tid & 15) << 2;       // float4 column offset
        int row = rowBase + rl;         // always < N_TOT (exact grid)
        float4 acc = make_float4(0.f, 0.f, 0.f, 0.f);
        int s0 = g_rowptr[row];
        int e0 = g_rowptr[row + 1];
        int j = s0;
        for (; j + 4 <= e0; j += 4) {
            int2 a  = g_csr[j];
            int2 b  = g_csr[j + 1];
            int2 cc = g_csr[j + 2];
            int2 dd = g_csr[j + 3];
            float4 va = __ldg((const float4*)&ego_in[a.x * D + c]);
            float4 vb = __ldg((const float4*)&ego_in[b.x * D + c]);
            float4 vc = __ldg((const float4*)&ego_in[cc.x * D + c]);
            float4 vd = __ldg((const float4*)&ego_in[dd.x * D + c]);
            float fa = __int_as_float(a.y);
            float fb = __int_as_float(b.y);
            float fc = __int_as_float(cc.y);
            float fd = __int_as_float(dd.y);
            acc.x += fa * va.x + fb * vb.x + fc * vc.x + fd * vd.x;
            acc.y += fa * va.y + fb * vb.y + fc * vc.y + fd * vd.y;
            acc.z += fa * va.z + fb * vb.z + fc * vc.z + fd * vd.z;
            acc.w += fa * va.w + fb * vb.w + fc * vc.w + fd * vd.w;
        }
        for (; j < e0; j++) {
            int2 a = g_csr[j];
            float4 va = __ldg((const float4*)&ego_in[a.x * D + c]);
            float fa = __int_as_float(a.y);
            acc.x += fa * va.x; acc.y += fa * va.y;
            acc.z += fa * va.z; acc.w += fa * va.w;
        }
        float4 e = *(const float4*)&ego_in[row * D + c];

        float li[4] = {acc.x + e.x, acc.y + e.y, acc.z + e.z, acc.w + e.w};
        float bi[4] = {acc.x * e.x, acc.y * e.y, acc.z * e.z, acc.w * e.w};

        uint32_t h0 = pack_hi(li[0], li[1]);
        uint32_t h1 = pack_hi(li[2], li[3]);
        __nv_bfloat162 hh0 = *reinterpret_cast<__nv_bfloat162*>(&h0);
        __nv_bfloat162 hh1 = *reinterpret_cast<__nv_bfloat162*>(&h1);
        uint32_t l0 = pack_hi(li[0] - __bfloat162float(hh0.x),
                              li[1] - __bfloat162float(hh0.y));
        uint32_t l1 = pack_hi(li[2] - __bfloat162float(hh1.x),
                              li[3] - __bfloat162float(hh1.y));
        uint32_t h2 = pack_hi(bi[0], bi[1]);
        uint32_t h3 = pack_hi(bi[2], bi[3]);
        __nv_bfloat162 hh2 = *reinterpret_cast<__nv_bfloat162*>(&h2);
        __nv_bfloat162 hh3 = *reinterpret_cast<__nv_bfloat162*>(&h3);
        uint32_t l2 = pack_hi(bi[0] - __bfloat162float(hh2.x),
                              bi[1] - __bfloat162float(hh2.y));
        uint32_t l3 = pack_hi(bi[2] - __bfloat162float(hh3.x),
                              bi[3] - __bfloat162float(hh3.y));

        *(uint2*)&sAhi[rl * SAP + c]      = make_uint2(h0, h1);
        *(uint2*)&sAlo[rl * SAP + c]      = make_uint2(l0, l1);
        *(uint2*)&sAhi[rl * SAP + 64 + c] = make_uint2(h2, h3);
        *(uint2*)&sAlo[rl * SAP + 64 + c] = make_uint2(l2, l3);
    }
    __syncthreads();

    // ---- Phase 2: tensor-core GEMM, all smem operands ----
    int wid = tid >> 5, lane = tid & 31;
    int gid = lane >> 2, tig = lane & 3;
    int n = wid * 8 + gid;            // warp wid owns n-tile wid

    float C[4] = {0.f, 0.f, 0.f, 0.f};

    #pragma unroll
    for (int ks = 0; ks < 8; ks++) {
        int k0 = ks * 16 + 2 * tig;
        uint32_t ah0 = *(const uint32_t*)&sAhi[gid * SAP + k0];
        uint32_t ah1 = *(const uint32_t*)&sAhi[(gid + 8) * SAP + k0];
        uint32_t ah2 = *(const uint32_t*)&sAhi[gid * SAP + k0 + 8];
        uint32_t ah3 = *(const uint32_t*)&sAhi[(gid + 8) * SAP + k0 + 8];
        uint32_t al0 = *(const uint32_t*)&sAlo[gid * SAP + k0];
        uint32_t al1 = *(const uint32_t*)&sAlo[(gid + 8) * SAP + k0];
        uint32_t al2 = *(const uint32_t*)&sAlo[gid * SAP + k0 + 8];
        uint32_t al3 = *(const uint32_t*)&sAlo[(gid + 8) * SAP + k0 + 8];

        uint32_t bh0 = *(const uint32_t*)&sWhi[n * SWP + k0];
        uint32_t bh1 = *(const uint32_t*)&sWhi[n * SWP + k0 + 8];
        uint32_t bl0 = *(const uint32_t*)&sWlo[n * SWP + k0];
        uint32_t bl1 = *(const uint32_t*)&sWlo[n * SWP + k0 + 8];

        MMA_BF16(C, ah0, ah1, ah2, ah3, bh0, bh1);   // hi*hi
        MMA_BF16(C, ah0, ah1, ah2, ah3, bl0, bl1);   // hi*lo
        MMA_BF16(C, al0, al1, al2, al3, bh0, bh1);   // lo*hi
    }

    {
        int cb = wid * 8 + tig * 2;
        *(float2*)&sC[gid * 64 + cb]       = make_float2(C[0], C[1]);
        *(float2*)&sC[(gid + 8) * 64 + cb] = make_float2(C[2], C[3]);
    }
    __syncthreads();

    // ---- Phase 3: epilogue (1 row x 4 cols per thread) ----
    {
        int ty = tid >> 4;       // row 0..15
        int tx = tid & 15;       // cols 4tx..4tx+3
        float4 b4 = *(const float4*)&bb[4 * tx];
        float4 X = *(const float4*)&sC[ty * 64 + 4 * tx];

        // reference adds b_bi to BOTH branches -> 2*b
        float x0 = X.x + 2.f * b4.x, x1 = X.y + 2.f * b4.y;
        float x2 = X.z + 2.f * b4.z, x3 = X.w + 2.f * b4.w;

        x0 = x0 > 0.f ? x0 : 0.01f * x0;  x1 = x1 > 0.f ? x1 : 0.01f * x1;
        x2 = x2 > 0.f ? x2 : 0.01f * x2;  x3 = x3 > 0.f ? x3 : 0.01f * x3;

        float ss = x0 * x0 + x1 * x1 + x2 * x2 + x3 * x3;
        #pragma unroll
        for (int o = 8; o; o >>= 1)
            ss += __shfl_xor_sync(0xffffffffu, ss, o);
        float inv = 1.0f / fmaxf(sqrtf(ss), 1e-12f);

        int r0 = rowBase + ty;
        int co = (layer + 1) * D + 4 * tx;
        *(float4*)&ego_out[r0 * D + 4 * tx] = make_float4(x0, x1, x2, x3);
        *(float4*)&g_all[r0 * (4 * D) + co] =
            make_float4(x0 * inv, x1 * inv, x2 * inv, x3 * inv);
    }
}

// ---------------------------------------------------------------------------
__global__ void gather_kernel(const int* __restrict__ users,
                              const int* __restrict__ pos_items,
                              const int* __restrict__ neg_items,
                              float* __restrict__ out) {
    int idx = blockIdx.x * blockDim.x + threadIdx.x;  // 3*B*256
    if (idx >= 3 * B_SZ * (4 * D)) return;
    int which = idx / (B_SZ * 4 * D);
    int rem   = idx - which * (B_SZ * 4 * D);
    int b = rem >> 8;
    int c = rem & 255;
    int row;
    if (which == 0)      row = users[b];
    else if (which == 1) row = N_USER + pos_items[b];
    else                 row = N_USER + neg_items[b];
    out[idx] = g_all[row * (4 * D) + c];
}

// ---------------------------------------------------------------------------
extern "C" void kernel_launch(void* const* d_in, const int* in_sizes, int n_in,
                              void* d_out, int out_size) {
    const float* user_emb  = (const float*)d_in[0];
    const float* item_emb  = (const float*)d_in[1];
    const float* W_gc      = (const float*)d_in[2];
    const float* W_bi      = (const float*)d_in[3];
    const float* b_bi      = (const float*)d_in[4];
    const float* vals      = (const float*)d_in[5];
    const int*   rows      = (const int*)d_in[6];
    const int*   cols      = (const int*)d_in[7];
    const int*   users     = (const int*)d_in[8];
    const int*   pos_items = (const int*)d_in[9];
    const int*   neg_items = (const int*)d_in[10];
    float* out = (float*)d_out;

    init_kernel<<<(N_TOT * D + 255) / 256, 256>>>(user_emb, item_emb);
    wconv_kernel<<<N_LAYERS, 256>>>(W_gc, W_bi);

    hist_kernel<<<(NNZ + 255) / 256, 256>>>(rows);
    scan1_kernel<<<SCAN_NBLK, SCAN_B>>>();
    scan2_kernel<<<1, 256>>>();
    scan3_kernel<<<SCAN_NBLK, SCAN_B>>>();
    scatter_kernel<<<(NNZ + 255) / 256, 256>>>(vals, rows, cols);

    float* e0; float* e1;
    cudaGetSymbolAddress((void**)&e0, g_E0);
    cudaGetSymbolAddress((void**)&e1, g_E1);
    __nv_bfloat16* whi; __nv_bfloat16* wlo;
    cudaGetSymbolAddress((void**)&whi, g_Whi);
    cudaGetSymbolAddress((void**)&wlo, g_Wlo);

    for (int k = 0; k < N_LAYERS; k++) {
        const float* in   = (k & 1) ? e1 : e0;
        float*       outp = (k & 1) ? e0 : e1;
        fused_layer_kernel<<<LBLK, 256>>>(in, outp,
                                          whi + k * 64 * 128,
                                          wlo + k * 64 * 128,
                                          b_bi + k * D, k);
    }

    gather_kernel<<<(3 * B_SZ * 4 * D + 255) / 256, 256>>>(users, pos_items,
                                                           neg_items, out);
}